// round 13
// baseline (speedup 1.0000x reference)
#include <cuda_runtime.h>
#include <cstddef>

#define Bx 16
#define Lx 4096
#define Dx 1024
#define NSPLIT 64
#define ROWS_PER_SPLIT (Lx / NSPLIT)   // 64
#define SROWS 32                       // rows per score block (8 warps x 2 x 2 passes)

// ---- scratch (__device__ globals; no allocation allowed) ----
__device__ float g_df[Bx * Dx];               // dec_feature
__device__ float g_score[Bx * Lx];            // pre-softmax scores
__device__ float g_partial[Bx * NSPLIT * Dx]; // context partials

// d_out layout (float32): attn, context, new_coverage
#define ATTN_OFF 0
#define CTX_OFF  (Bx * Lx)
#define COV_OFF  (Bx * Lx + Bx * Dx)

__device__ __forceinline__ float tanh_approx(float x) {
    float y;
    asm("tanh.approx.f32 %0, %1;" : "=f"(y) : "f"(x));
    return y;
}

// ============================================================
// Kernel 1: dec_feature. grid (Dx, 2): block = one d, 8 batches. (R8)
// ============================================================
__global__ void k_decfeat(const float* __restrict__ dh,
                          const float* __restrict__ W,
                          const float* __restrict__ bias) {
    int d  = blockIdx.x;
    int bh = blockIdx.y;               // batch half: b in [8*bh, 8*bh+8)
    int t = threadIdx.x, warp = t >> 5, lane = t & 31;

    float4 w4 = ((const float4*)(W + (size_t)d * Dx))[t];

    float acc[8];
#pragma unroll
    for (int i = 0; i < 8; i++) {
        float4 h4 = ((const float4*)(dh + (size_t)(bh * 8 + i) * Dx))[t];
        acc[i] = w4.x * h4.x + w4.y * h4.y + w4.z * h4.z + w4.w * h4.w;
    }

    bool hi = (lane & 16) != 0;
#pragma unroll
    for (int i = 0; i < 4; i++) {
        float send = hi ? acc[i] : acc[i + 4];
        float r = __shfl_xor_sync(0xffffffffu, send, 16);
        acc[i] = (hi ? acc[i + 4] : acc[i]) + r;
    }
    bool h2 = (lane & 8) != 0;
#pragma unroll
    for (int i = 0; i < 2; i++) {
        float send = h2 ? acc[i] : acc[i + 2];
        float r = __shfl_xor_sync(0xffffffffu, send, 8);
        acc[i] = (h2 ? acc[i + 2] : acc[i]) + r;
    }
    bool h3 = (lane & 4) != 0;
    {
        float send = h3 ? acc[0] : acc[1];
        float r = __shfl_xor_sync(0xffffffffu, send, 4);
        acc[0] = (h3 ? acc[1] : acc[0]) + r;
    }
    acc[0] += __shfl_xor_sync(0xffffffffu, acc[0], 2);
    acc[0] += __shfl_xor_sync(0xffffffffu, acc[0], 1);

    __shared__ float s[8][8];
    if ((lane & 3) == 0) s[warp][(lane >> 2) & 7] = acc[0];
    __syncthreads();
    if (t < 8) {
        float v = 0.f;
#pragma unroll
        for (int w = 0; w < 8; w++) v += s[w][t];
        g_df[(bh * 8 + t) * Dx + d] = v + bias[d];
    }
}

// ============================================================
// Kernel 2: score. Block = 32 rows; warp runs the proven 2-row
// interleaved pattern TWICE sequentially ({w,w+8} then {w+16,w+24}).
// Halves block count -> preamble amortized 2x; register shape = R8.
// ============================================================
__global__ void k_score(const float* __restrict__ ef,
                        const float* __restrict__ cov,
                        const float* __restrict__ wscore,
                        const float* __restrict__ wcov) {
    int b  = blockIdx.y;
    int l0 = blockIdx.x * SROWS;
    int t  = threadIdx.x;
    int warp = t >> 5, lane = t & 31;

    // cov prefetch (before barrier; overlaps smem fill)
    float cpre[4];
#pragma unroll
    for (int p = 0; p < 4; p++)
        cpre[p] = cov[b * Lx + l0 + warp + p * 8];

    __shared__ float4 s_df[Dx / 4], s_ws[Dx / 4], s_wc[Dx / 4];
    s_df[t] = ((const float4*)(g_df + (size_t)b * Dx))[t];
    s_ws[t] = ((const float4*)wscore)[t];
    s_wc[t] = ((const float4*)wcov)[t];
    __syncthreads();

#pragma unroll
    for (int pass = 0; pass < 2; pass++) {
        int lA = l0 + pass * 16 + warp;
        int lB = lA + 8;
        float cA = cpre[pass * 2];
        float cB = cpre[pass * 2 + 1];
        const float4* rowA = (const float4*)(ef + ((size_t)b * Lx + lA) * Dx);
        const float4* rowB = (const float4*)(ef + ((size_t)b * Lx + lB) * Dx);

        float sumA = 0.f, sumB = 0.f;
#pragma unroll
        for (int j = 0; j < 8; j++) {
            int idx = lane + j * 32;
            float4 eA = __ldcs(&rowA[idx]);
            float4 eB = __ldcs(&rowB[idx]);
            float4 dv = s_df[idx];
            float4 wc = s_wc[idx];
            float4 ws = s_ws[idx];
            sumA += tanh_approx(fmaf(cA, wc.x, eA.x + dv.x)) * ws.x
                  + tanh_approx(fmaf(cA, wc.y, eA.y + dv.y)) * ws.y
                  + tanh_approx(fmaf(cA, wc.z, eA.z + dv.z)) * ws.z
                  + tanh_approx(fmaf(cA, wc.w, eA.w + dv.w)) * ws.w;
            sumB += tanh_approx(fmaf(cB, wc.x, eB.x + dv.x)) * ws.x
                  + tanh_approx(fmaf(cB, wc.y, eB.y + dv.y)) * ws.y
                  + tanh_approx(fmaf(cB, wc.z, eB.z + dv.z)) * ws.z
                  + tanh_approx(fmaf(cB, wc.w, eB.w + dv.w)) * ws.w;
        }
#pragma unroll
        for (int off = 16; off; off >>= 1) {
            sumA += __shfl_down_sync(0xffffffffu, sumA, off);
            sumB += __shfl_down_sync(0xffffffffu, sumB, off);
        }
        if (lane == 0) {
            g_score[b * Lx + lA] = sumA;
            g_score[b * Lx + lB] = sumB;
        }
    }
}

// ============================================================
// Kernel 3: masked softmax + renormalize -> attn & new_coverage. (R8)
// ============================================================
__global__ void k_softmax(const float* __restrict__ mask,
                          const float* __restrict__ cov,
                          float* __restrict__ out) {
    int b = blockIdx.x;
    int t = threadIdx.x;
    __shared__ float red[32];
    __shared__ float bcast;

    float s[4], em[4];
#pragma unroll
    for (int i = 0; i < 4; i++) s[i] = g_score[b * Lx + t + i * 1024];

    float mx = fmaxf(fmaxf(s[0], s[1]), fmaxf(s[2], s[3]));
#pragma unroll
    for (int off = 16; off; off >>= 1)
        mx = fmaxf(mx, __shfl_xor_sync(0xffffffffu, mx, off));
    if ((t & 31) == 0) red[t >> 5] = mx;
    __syncthreads();
    if (t < 32) {
        float v = red[t];
#pragma unroll
        for (int off = 16; off; off >>= 1)
            v = fmaxf(v, __shfl_xor_sync(0xffffffffu, v, off));
        if (t == 0) bcast = v;
    }
    __syncthreads();
    mx = bcast;

    float lsum = 0.f;
#pragma unroll
    for (int i = 0; i < 4; i++) {
        em[i] = expf(s[i] - mx) * mask[b * Lx + t + i * 1024];
        lsum += em[i];
    }
#pragma unroll
    for (int off = 16; off; off >>= 1)
        lsum += __shfl_xor_sync(0xffffffffu, lsum, off);
    __syncthreads();
    if ((t & 31) == 0) red[t >> 5] = lsum;
    __syncthreads();
    if (t < 32) {
        float v = red[t];
#pragma unroll
        for (int off = 16; off; off >>= 1)
            v += __shfl_xor_sync(0xffffffffu, v, off);
        if (t == 0) bcast = v;
    }
    __syncthreads();
    float inv = 1.f / bcast;

#pragma unroll
    for (int i = 0; i < 4; i++) {
        int idx = b * Lx + t + i * 1024;
        float a = em[i] * inv;
        out[ATTN_OFF + idx] = a;
        out[COV_OFF  + idx] = a + cov[idx];
    }
}

// ============================================================
// Kernel 4: context partials. grid = (NSPLIT, Bx), 256 threads. (R8)
// ============================================================
__global__ void k_context(const float* __restrict__ eo,
                          const float* __restrict__ attn) {
    int b  = blockIdx.y;
    int sp = blockIdx.x;     // 0..NSPLIT-1
    int t  = threadIdx.x;    // 0..255
    int l0 = sp * ROWS_PER_SPLIT;

    __shared__ float sa[ROWS_PER_SPLIT];
    if (t < ROWS_PER_SPLIT) sa[t] = attn[b * Lx + l0 + t];
    __syncthreads();

    const float4* base = (const float4*)eo + ((size_t)b * Lx + l0) * (Dx / 4) + t;
    float4 acc = make_float4(0.f, 0.f, 0.f, 0.f);
#pragma unroll 8
    for (int i = 0; i < ROWS_PER_SPLIT; i++) {
        float a = sa[i];
        float4 v = __ldcs(base + (size_t)i * (Dx / 4));
        acc.x = fmaf(a, v.x, acc.x);
        acc.y = fmaf(a, v.y, acc.y);
        acc.z = fmaf(a, v.z, acc.z);
        acc.w = fmaf(a, v.w, acc.w);
    }
    ((float4*)(g_partial + ((size_t)(b * NSPLIT + sp)) * Dx))[t] = acc;
}

// ============================================================
// Kernel 5: partial reduce, high-occupancy (R12).
// ============================================================
__global__ void k_reduce(float* __restrict__ out) {
    int t = threadIdx.x;
    int o4  = t >> 3;                       // 0..31
    int grp = t & 7;                        // 0..7
    int q = blockIdx.x * 32 + o4;           // global float4 output id
    int b = q >> 8;
    int dq = q & 255;

    const float4* pbase = (const float4*)g_partial + ((size_t)b * NSPLIT) * (Dx / 4) + dq;
    float4 acc = make_float4(0.f, 0.f, 0.f, 0.f);
#pragma unroll
    for (int i = 0; i < 8; i++) {
        float4 p = pbase[(size_t)(grp * 8 + i) * (Dx / 4)];
        acc.x += p.x; acc.y += p.y; acc.z += p.z; acc.w += p.w;
    }

    __shared__ float4 sm[32][8];
    sm[o4][grp] = acc;
    __syncthreads();

    if (grp == 0) {
        float4 sum = sm[o4][0];
#pragma unroll
        for (int g = 1; g < 8; g++) {
            float4 p = sm[o4][g];
            sum.x += p.x; sum.y += p.y; sum.z += p.z; sum.w += p.w;
        }
        ((float4*)(out + CTX_OFF))[q] = sum;
    }
}

// ============================================================
extern "C" void kernel_launch(void* const* d_in, const int* in_sizes, int n_in,
                              void* d_out, int out_size) {
    const float* dec_hidden  = (const float*)d_in[0];
    const float* enc_output  = (const float*)d_in[1];
    const float* enc_feature = (const float*)d_in[2];
    const float* enc_mask    = (const float*)d_in[3];
    // d_in[4] = sec_attn : dead code in reference
    const float* coverage    = (const float*)d_in[5];
    const float* W_feat      = (const float*)d_in[6];
    const float* b_feat      = (const float*)d_in[7];
    const float* w_score     = (const float*)d_in[8];
    const float* w_cov       = (const float*)d_in[9];
    float* out = (float*)d_out;

    k_decfeat<<<dim3(Dx, 2), 256>>>(dec_hidden, W_feat, b_feat);
    k_score  <<<dim3(Lx / SROWS, Bx), 256>>>(enc_feature, coverage, w_score, w_cov);
    k_softmax<<<Bx, 1024>>>(enc_mask, coverage, out);
    k_context<<<dim3(NSPLIT, Bx), 256>>>(enc_output, out + ATTN_OFF);
    k_reduce <<<128, 256>>>(out);
}

// round 14
// speedup vs baseline: 1.0401x; 1.0401x over previous
#include <cuda_runtime.h>
#include <cstddef>

#define Bx 16
#define Lx 4096
#define Dx 1024
#define NSPLIT 64
#define ROWS_PER_SPLIT (Lx / NSPLIT)   // 64
#define SROWS 16                       // rows per score block (8 warps x 2) — R8-proven

// ---- scratch (__device__ globals; no allocation allowed) ----
__device__ float g_df[Bx * Dx];               // dec_feature
__device__ float g_score[Bx * Lx];            // pre-softmax scores
__device__ float g_partial[Bx * NSPLIT * Dx]; // context partials

// d_out layout (float32): attn, context, new_coverage
#define ATTN_OFF 0
#define CTX_OFF  (Bx * Lx)
#define COV_OFF  (Bx * Lx + Bx * Dx)

__device__ __forceinline__ float tanh_approx(float x) {
    float y;
    asm("tanh.approx.f32 %0, %1;" : "=f"(y) : "f"(x));
    return y;
}

// ============================================================
// Kernel 1: dec_feature. grid (Dx, 2): block = one d, 8 batches. (R8)
// ============================================================
__global__ void k_decfeat(const float* __restrict__ dh,
                          const float* __restrict__ W,
                          const float* __restrict__ bias) {
    int d  = blockIdx.x;
    int bh = blockIdx.y;               // batch half: b in [8*bh, 8*bh+8)
    int t = threadIdx.x, warp = t >> 5, lane = t & 31;

    float4 w4 = ((const float4*)(W + (size_t)d * Dx))[t];

    float acc[8];
#pragma unroll
    for (int i = 0; i < 8; i++) {
        float4 h4 = ((const float4*)(dh + (size_t)(bh * 8 + i) * Dx))[t];
        acc[i] = w4.x * h4.x + w4.y * h4.y + w4.z * h4.z + w4.w * h4.w;
    }

    bool hi = (lane & 16) != 0;
#pragma unroll
    for (int i = 0; i < 4; i++) {
        float send = hi ? acc[i] : acc[i + 4];
        float r = __shfl_xor_sync(0xffffffffu, send, 16);
        acc[i] = (hi ? acc[i + 4] : acc[i]) + r;
    }
    bool h2 = (lane & 8) != 0;
#pragma unroll
    for (int i = 0; i < 2; i++) {
        float send = h2 ? acc[i] : acc[i + 2];
        float r = __shfl_xor_sync(0xffffffffu, send, 8);
        acc[i] = (h2 ? acc[i + 2] : acc[i]) + r;
    }
    bool h3 = (lane & 4) != 0;
    {
        float send = h3 ? acc[0] : acc[1];
        float r = __shfl_xor_sync(0xffffffffu, send, 4);
        acc[0] = (h3 ? acc[1] : acc[0]) + r;
    }
    acc[0] += __shfl_xor_sync(0xffffffffu, acc[0], 2);
    acc[0] += __shfl_xor_sync(0xffffffffu, acc[0], 1);

    __shared__ float s[8][8];
    if ((lane & 3) == 0) s[warp][(lane >> 2) & 7] = acc[0];
    __syncthreads();
    if (t < 8) {
        float v = 0.f;
#pragma unroll
        for (int w = 0; w < 8; w++) v += s[w][t];
        g_df[(bh * 8 + t) * Dx + d] = v + bias[d];
    }
}

// ============================================================
// Kernel 2: score. Block = 16 rows; warp = 2 rows interleaved
// (w and w+8). ONE pass per warp (multi-pass measured slower).
// cov loads hoisted above the barrier to overlap smem fill.
// ============================================================
__global__ void k_score(const float* __restrict__ ef,
                        const float* __restrict__ cov,
                        const float* __restrict__ wscore,
                        const float* __restrict__ wcov) {
    int b  = blockIdx.y;
    int l0 = blockIdx.x * SROWS;
    int t  = threadIdx.x;
    int warp = t >> 5, lane = t & 31;

    int lA = l0 + warp;
    int lB = lA + 8;
    float cA = cov[b * Lx + lA];          // before barrier: overlaps smem fill
    float cB = cov[b * Lx + lB];
    const float4* rowA = (const float4*)(ef + ((size_t)b * Lx + lA) * Dx);
    const float4* rowB = (const float4*)(ef + ((size_t)b * Lx + lB) * Dx);

    __shared__ float4 s_df[Dx / 4], s_ws[Dx / 4], s_wc[Dx / 4];
    s_df[t] = ((const float4*)(g_df + (size_t)b * Dx))[t];
    s_ws[t] = ((const float4*)wscore)[t];
    s_wc[t] = ((const float4*)wcov)[t];
    __syncthreads();

    float sumA = 0.f, sumB = 0.f;
#pragma unroll
    for (int j = 0; j < 8; j++) {
        int idx = lane + j * 32;
        float4 eA = __ldcs(&rowA[idx]);
        float4 eB = __ldcs(&rowB[idx]);
        float4 dv = s_df[idx];
        float4 wc = s_wc[idx];
        float4 ws = s_ws[idx];
        sumA += tanh_approx(fmaf(cA, wc.x, eA.x + dv.x)) * ws.x
              + tanh_approx(fmaf(cA, wc.y, eA.y + dv.y)) * ws.y
              + tanh_approx(fmaf(cA, wc.z, eA.z + dv.z)) * ws.z
              + tanh_approx(fmaf(cA, wc.w, eA.w + dv.w)) * ws.w;
        sumB += tanh_approx(fmaf(cB, wc.x, eB.x + dv.x)) * ws.x
              + tanh_approx(fmaf(cB, wc.y, eB.y + dv.y)) * ws.y
              + tanh_approx(fmaf(cB, wc.z, eB.z + dv.z)) * ws.z
              + tanh_approx(fmaf(cB, wc.w, eB.w + dv.w)) * ws.w;
    }
#pragma unroll
    for (int off = 16; off; off >>= 1) {
        sumA += __shfl_down_sync(0xffffffffu, sumA, off);
        sumB += __shfl_down_sync(0xffffffffu, sumB, off);
    }
    if (lane == 0) {
        g_score[b * Lx + lA] = sumA;
        g_score[b * Lx + lB] = sumB;
    }
}

// ============================================================
// Kernel 3: masked softmax + renormalize -> attn & new_coverage. (R8)
// softmax -> *mask -> /sum collapses to e*m / sum(e*m).
// ============================================================
__global__ void k_softmax(const float* __restrict__ mask,
                          const float* __restrict__ cov,
                          float* __restrict__ out) {
    int b = blockIdx.x;
    int t = threadIdx.x;
    __shared__ float red[32];
    __shared__ float bcast;

    float s[4], em[4];
#pragma unroll
    for (int i = 0; i < 4; i++) s[i] = g_score[b * Lx + t + i * 1024];

    float mx = fmaxf(fmaxf(s[0], s[1]), fmaxf(s[2], s[3]));
#pragma unroll
    for (int off = 16; off; off >>= 1)
        mx = fmaxf(mx, __shfl_xor_sync(0xffffffffu, mx, off));
    if ((t & 31) == 0) red[t >> 5] = mx;
    __syncthreads();
    if (t < 32) {
        float v = red[t];
#pragma unroll
        for (int off = 16; off; off >>= 1)
            v = fmaxf(v, __shfl_xor_sync(0xffffffffu, v, off));
        if (t == 0) bcast = v;
    }
    __syncthreads();
    mx = bcast;

    float lsum = 0.f;
#pragma unroll
    for (int i = 0; i < 4; i++) {
        em[i] = expf(s[i] - mx) * mask[b * Lx + t + i * 1024];
        lsum += em[i];
    }
#pragma unroll
    for (int off = 16; off; off >>= 1)
        lsum += __shfl_xor_sync(0xffffffffu, lsum, off);
    __syncthreads();
    if ((t & 31) == 0) red[t >> 5] = lsum;
    __syncthreads();
    if (t < 32) {
        float v = red[t];
#pragma unroll
        for (int off = 16; off; off >>= 1)
            v += __shfl_xor_sync(0xffffffffu, v, off);
        if (t == 0) bcast = v;
    }
    __syncthreads();
    float inv = 1.f / bcast;

#pragma unroll
    for (int i = 0; i < 4; i++) {
        int idx = b * Lx + t + i * 1024;
        float a = em[i] * inv;
        out[ATTN_OFF + idx] = a;
        out[COV_OFF  + idx] = a + cov[idx];
    }
}

// ============================================================
// Kernel 4: context partials. grid = (NSPLIT, Bx), 256 threads. (R8)
// ============================================================
__global__ void k_context(const float* __restrict__ eo,
                          const float* __restrict__ attn) {
    int b  = blockIdx.y;
    int sp = blockIdx.x;     // 0..NSPLIT-1
    int t  = threadIdx.x;    // 0..255
    int l0 = sp * ROWS_PER_SPLIT;

    __shared__ float sa[ROWS_PER_SPLIT];
    if (t < ROWS_PER_SPLIT) sa[t] = attn[b * Lx + l0 + t];
    __syncthreads();

    const float4* base = (const float4*)eo + ((size_t)b * Lx + l0) * (Dx / 4) + t;
    float4 acc = make_float4(0.f, 0.f, 0.f, 0.f);
#pragma unroll 8
    for (int i = 0; i < ROWS_PER_SPLIT; i++) {
        float a = sa[i];
        float4 v = __ldcs(base + (size_t)i * (Dx / 4));
        acc.x = fmaf(a, v.x, acc.x);
        acc.y = fmaf(a, v.y, acc.y);
        acc.z = fmaf(a, v.z, acc.z);
        acc.w = fmaf(a, v.w, acc.w);
    }
    ((float4*)(g_partial + ((size_t)(b * NSPLIT + sp)) * Dx))[t] = acc;
}

// ============================================================
// Kernel 5: partial reduce, high-occupancy (R12).
// 128 blocks x 256 threads; 8 threads per float4 output, each sums
// 8 partials (fixed order), then fixed-order smem merge. Deterministic.
// ============================================================
__global__ void k_reduce(float* __restrict__ out) {
    int t = threadIdx.x;
    int o4  = t >> 3;                       // 0..31
    int grp = t & 7;                        // 0..7
    int q = blockIdx.x * 32 + o4;           // global float4 output id
    int b = q >> 8;
    int dq = q & 255;

    const float4* pbase = (const float4*)g_partial + ((size_t)b * NSPLIT) * (Dx / 4) + dq;
    float4 acc = make_float4(0.f, 0.f, 0.f, 0.f);
#pragma unroll
    for (int i = 0; i < 8; i++) {
        float4 p = pbase[(size_t)(grp * 8 + i) * (Dx / 4)];
        acc.x += p.x; acc.y += p.y; acc.z += p.z; acc.w += p.w;
    }

    __shared__ float4 sm[32][8];
    sm[o4][grp] = acc;
    __syncthreads();

    if (grp == 0) {
        float4 sum = sm[o4][0];
#pragma unroll
        for (int g = 1; g < 8; g++) {
            float4 p = sm[o4][g];
            sum.x += p.x; sum.y += p.y; sum.z += p.z; sum.w += p.w;
        }
        ((float4*)(out + CTX_OFF))[q] = sum;
    }
}

// ============================================================
extern "C" void kernel_launch(void* const* d_in, const int* in_sizes, int n_in,
                              void* d_out, int out_size) {
    const float* dec_hidden  = (const float*)d_in[0];
    const float* enc_output  = (const float*)d_in[1];
    const float* enc_feature = (const float*)d_in[2];
    const float* enc_mask    = (const float*)d_in[3];
    // d_in[4] = sec_attn : dead code in reference
    const float* coverage    = (const float*)d_in[5];
    const float* W_feat      = (const float*)d_in[6];
    const float* b_feat      = (const float*)d_in[7];
    const float* w_score     = (const float*)d_in[8];
    const float* w_cov       = (const float*)d_in[9];
    float* out = (float*)d_out;

    k_decfeat<<<dim3(Dx, 2), 256>>>(dec_hidden, W_feat, b_feat);
    k_score  <<<dim3(Lx / SROWS, Bx), 256>>>(enc_feature, coverage, w_score, w_cov);
    k_softmax<<<Bx, 1024>>>(enc_mask, coverage, out);
    k_context<<<dim3(NSPLIT, Bx), 256>>>(enc_output, out + ATTN_OFF);
    k_reduce <<<128, 256>>>(out);
}